// round 5
// baseline (speedup 1.0000x reference)
#include <cuda_runtime.h>
#include <cuda_fp16.h>
#include <cuda_bf16.h>

#define N_NODES 100000
#define N_EDGES 20000
#define N_INC   800000
#define TD      384
#define HID     128
#define NPART   1024
#define NBE     79
#define NBN     391
#define NBI     3125

// ---------------- device scratch ----------------
__device__ __align__(16) __half g_h16A[N_NODES * HID];
__device__ __align__(16) __half g_h16B[N_NODES * HID];
__device__ __align__(16) __half g_ef16[N_EDGES * HID];
__device__ __align__(16) __nv_bfloat16 g_WtH[HID * TD];
__device__ __align__(16) __nv_bfloat16 g_WtL[HID * TD];
__device__ int   g_ecnt[N_EDGES];
__device__ int   g_ncnt[N_NODES];
__device__ int   g_ecur[N_EDGES];
__device__ int   g_ncur[N_NODES];
__device__ int   g_eoff[N_EDGES + 1];
__device__ int   g_noff[N_NODES + 1];
__device__ int   g_enodes[N_INC];
__device__ int   g_nedges[N_INC];
__device__ int   g_bsumE[128];
__device__ int   g_bsumN[512];
__device__ float g_part[NPART * HID];
__device__ __align__(16) float g_scale[HID];

// ---------------- CSR construction ----------------
__global__ void zero_counts() {
    int i = blockIdx.x * blockDim.x + threadIdx.x;
    if (i < N_EDGES) { g_ecnt[i] = 0; g_ecur[i] = 0; }
    if (i < N_NODES) { g_ncnt[i] = 0; g_ncur[i] = 0; }
}

__global__ void hist_kernel(const int* __restrict__ ni, const int* __restrict__ ei) {
    int i = blockIdx.x * blockDim.x + threadIdx.x;
    if (i < N_INC) {
        atomicAdd(&g_ecnt[ei[i]], 1);
        atomicAdd(&g_ncnt[ni[i]], 1);
    }
}

__global__ void segB() {
    int b = blockIdx.x;
    const int* __restrict__ cnt;
    int n;
    int* bs;
    if (b < NBE) { cnt = g_ecnt; n = N_EDGES; bs = g_bsumE; }
    else { b -= NBE; cnt = g_ncnt; n = N_NODES; bs = g_bsumN; }
    __shared__ int s[256];
    int t = threadIdx.x;
    int i = b * 256 + t;
    s[t] = (i < n) ? cnt[i] : 0;
    __syncthreads();
    for (int o = 128; o > 0; o >>= 1) {
        if (t < o) s[t] += s[t + o];
        __syncthreads();
    }
    if (t == 0) bs[b] = s[0];
}

__global__ void scanB() {
    int* bs = blockIdx.x ? g_bsumN : g_bsumE;
    int nb = blockIdx.x ? NBN : NBE;
    __shared__ int s[512];
    int t = threadIdx.x;
    int v = (t < nb) ? bs[t] : 0;
    s[t] = v;
    __syncthreads();
    for (int o = 1; o < 512; o <<= 1) {
        int x = (t >= o) ? s[t - o] : 0;
        __syncthreads();
        s[t] += x;
        __syncthreads();
    }
    if (t < nb) bs[t] = s[t] - v;
}

__global__ void scanfB() {
    int b = blockIdx.x;
    const int* __restrict__ cnt;
    const int* bs;
    int* off;
    int n;
    if (b < NBE) { cnt = g_ecnt; bs = g_bsumE; off = g_eoff; n = N_EDGES; }
    else { b -= NBE; cnt = g_ncnt; bs = g_bsumN; off = g_noff; n = N_NODES; }
    __shared__ int s[256];
    int t = threadIdx.x;
    int i = b * 256 + t;
    int v = (i < n) ? cnt[i] : 0;
    s[t] = v;
    __syncthreads();
    for (int o = 1; o < 256; o <<= 1) {
        int x = (t >= o) ? s[t - o] : 0;
        __syncthreads();
        s[t] += x;
        __syncthreads();
    }
    if (i < n) off[i] = bs[b] + s[t] - v;
    if (i == 0) off[n] = N_INC;
}

__global__ void csr_fill(const int* __restrict__ ni, const int* __restrict__ ei) {
    int i = blockIdx.x * blockDim.x + threadIdx.x;
    if (i >= N_INC) return;
    int e = ei[i], n = ni[i];
    int pe = g_eoff[e] + atomicAdd(&g_ecur[e], 1);
    g_enodes[pe] = n;
    int pn = g_noff[n] + atomicAdd(&g_ncur[n], 1);
    g_nedges[pn] = e;
}

// ---------------- W prep ----------------
__global__ void w_prep(const float* __restrict__ W) {
    int i = blockIdx.x * blockDim.x + threadIdx.x;
    if (i >= TD * HID) return;
    int n = i & (HID - 1);
    int k = i >> 7;
    float x = W[k * HID + n];
    __nv_bfloat16 hi = __float2bfloat16(x);
    float lo = x - __bfloat162float(hi);
    g_WtH[n * TD + k] = hi;
    g_WtL[n * TD + k] = __float2bfloat16(lo);
}

// ---------------- tensor-core projection GEMM (bf16-split, pipelined) ----------------
#define SSTR 72
#define KT   64
#define NKT  (TD / KT)               // 6
#define ATILE (128 * SSTR)           // halves
#define WBUF  (2 * 128 * SSTR)       // halves per W buffer (hi+lo)

#define LDSM4(r, addr) \
    asm volatile("ldmatrix.sync.aligned.m8n8.x4.shared.b16 {%0,%1,%2,%3}, [%4];" \
        : "=r"((r)[0]), "=r"((r)[1]), "=r"((r)[2]), "=r"((r)[3]) : "r"(addr))

#define MMA16816(c, a, b0, b1) \
    asm volatile("mma.sync.aligned.m16n8k16.row.col.f32.bf16.bf16.f32 " \
        "{%0,%1,%2,%3},{%4,%5,%6,%7},{%8,%9},{%0,%1,%2,%3};" \
        : "+f"((c)[0]), "+f"((c)[1]), "+f"((c)[2]), "+f"((c)[3]) \
        : "r"((a)[0]), "r"((a)[1]), "r"((a)[2]), "r"((a)[3]), "r"(b0), "r"(b1))

#define CPA16(dst, src) \
    asm volatile("cp.async.cg.shared.global [%0], [%1], 16;" :: "r"(dst), "l"(src))
#define CPA_COMMIT() asm volatile("cp.async.commit_group;")
#define CPA_WAIT1()  asm volatile("cp.async.wait_group 1;")
#define CPA_WAIT0()  asm volatile("cp.async.wait_group 0;")

__global__ void __launch_bounds__(256, 2) gemm_mma(
    const float* __restrict__ A, const float* __restrict__ bias) {
    extern __shared__ char dynsmem[];
    __nv_bfloat16* sAH = (__nv_bfloat16*)dynsmem;           // [128][72]
    __nv_bfloat16* sAL = sAH + ATILE;

    const int tid = threadIdx.x;
    const int lane = tid & 31;
    const int wid = tid >> 5;
    const int wr = wid >> 1;
    const int wc = wid & 1;
    const int bm = blockIdx.x * 128;

    const unsigned sb = (unsigned)__cvta_generic_to_shared(dynsmem);
    const unsigned AHb = sb;
    const unsigned ALb = sb + ATILE * 2;
    const unsigned Wb0 = sb + 2 * ATILE * 2;                // W buffers base

    const int aRow = ((lane >> 3) & 1) * 8 + (lane & 7);
    const int aColH = (lane >> 4) * 8;
    const unsigned aOff0 = (unsigned)(((wr * 32 + 0  + aRow) * SSTR + aColH) * 2);
    const unsigned aOff1 = (unsigned)(((wr * 32 + 16 + aRow) * SSTR + aColH) * 2);
    const int bRow = (lane >> 4) * 8 + (lane & 7);
    const int bColH = ((lane >> 3) & 1) * 8;
    const unsigned bOff = (unsigned)(((wc * 64 + bRow) * SSTR + bColH) * 2);

    const int lm = tid >> 1;
    const int lk = (tid & 1) * 32;
    int arow = bm + lm;
    if (arow >= N_NODES) arow = N_NODES - 1;
    const float* Ap = A + (size_t)arow * TD + lk;
    const __nv_bfloat16* WHp = g_WtH + lm * TD + lk;
    const __nv_bfloat16* WLp = g_WtL + lm * TD + lk;
    const unsigned wDst = (unsigned)((lm * SSTR + lk) * 2); // byte offset within buffer half

    float4 Areg[8];

    // W cp.async for tile t into buffer b
    auto cpW = [&](int t, int b) {
        unsigned base = Wb0 + (unsigned)b * (WBUF * 2);
#pragma unroll
        for (int cc = 0; cc < 4; cc++) {
            CPA16(base + wDst + cc * 16, WHp + t * KT + cc * 8);
            CPA16(base + ATILE * 2 + wDst + cc * 16, WLp + t * KT + cc * 8);
        }
        CPA_COMMIT();
    };
    auto loadA = [&](int t) {
#pragma unroll
        for (int cc = 0; cc < 8; cc++)
            Areg[cc] = *(const float4*)(Ap + t * KT + cc * 4);
    };
    auto cvtStoreA = [&]() {
#pragma unroll
        for (int cc = 0; cc < 8; cc++) {
            float4 v = Areg[cc];
            __nv_bfloat16 h0 = __float2bfloat16(v.x);
            __nv_bfloat16 h1 = __float2bfloat16(v.y);
            __nv_bfloat16 h2 = __float2bfloat16(v.z);
            __nv_bfloat16 h3 = __float2bfloat16(v.w);
            __nv_bfloat162 hA, hB, lA, lB;
            hA.x = h0; hA.y = h1; hB.x = h2; hB.y = h3;
            lA.x = __float2bfloat16(v.x - __bfloat162float(h0));
            lA.y = __float2bfloat16(v.y - __bfloat162float(h1));
            lB.x = __float2bfloat16(v.z - __bfloat162float(h2));
            lB.y = __float2bfloat16(v.w - __bfloat162float(h3));
            int so = lm * SSTR + lk + cc * 4;
            *(__nv_bfloat162*)(sAH + so)     = hA;
            *(__nv_bfloat162*)(sAH + so + 2) = hB;
            *(__nv_bfloat162*)(sAL + so)     = lA;
            *(__nv_bfloat162*)(sAL + so + 2) = lB;
        }
    };

    float c[2][8][4];
#pragma unroll
    for (int i = 0; i < 2; i++)
#pragma unroll
        for (int j = 0; j < 8; j++)
#pragma unroll
            for (int q = 0; q < 4; q++) c[i][j][q] = 0.f;

    // prologue
    loadA(0);
    cpW(0, 0);

    for (int t = 0; t < NKT; t++) {
        cvtStoreA();                       // A(t) regs -> smem (prev compute done)
        if (t + 1 < NKT) {
            cpW(t + 1, (t + 1) & 1);       // W(t+1) in flight during compute(t)
            loadA(t + 1);                  // A(t+1) LDG in flight during compute(t)
            CPA_WAIT1();                   // W(t) landed
        } else {
            CPA_WAIT0();
        }
        __syncthreads();

        const unsigned WHbase = Wb0 + (unsigned)(t & 1) * (WBUF * 2);
        const unsigned WLbase = WHbase + ATILE * 2;
#pragma unroll
        for (int kk = 0; kk < KT / 16; kk++) {
            const unsigned ko = kk * 32;
            unsigned aH[2][4], aL[2][4];
            LDSM4(aH[0], AHb + aOff0 + ko);
            LDSM4(aH[1], AHb + aOff1 + ko);
            LDSM4(aL[0], ALb + aOff0 + ko);
            LDSM4(aL[1], ALb + aOff1 + ko);
#pragma unroll
            for (int jj = 0; jj < 4; jj++) {
                unsigned bH[4], bL[4];
                const unsigned bo = bOff + jj * (16 * SSTR * 2) + ko;
                LDSM4(bH, WHbase + bo);
                LDSM4(bL, WLbase + bo);
#pragma unroll
                for (int i = 0; i < 2; i++) {
                    MMA16816(c[i][2 * jj],     aH[i], bH[0], bH[1]);
                    MMA16816(c[i][2 * jj],     aH[i], bL[0], bL[1]);
                    MMA16816(c[i][2 * jj],     aL[i], bH[0], bH[1]);
                    MMA16816(c[i][2 * jj + 1], aH[i], bH[2], bH[3]);
                    MMA16816(c[i][2 * jj + 1], aH[i], bL[2], bL[3]);
                    MMA16816(c[i][2 * jj + 1], aL[i], bH[2], bH[3]);
                }
            }
        }
        if (t + 1 < NKT) __syncthreads();  // protect smem before next store
    }

#pragma unroll
    for (int i = 0; i < 2; i++) {
        int r0 = bm + wr * 32 + i * 16 + (lane >> 2);
        int r1 = r0 + 8;
#pragma unroll
        for (int j = 0; j < 8; j++) {
            int n = wc * 64 + j * 8 + (lane & 3) * 2;
            float2 bb = *(const float2*)(bias + n);
            __half2 v0 = __floats2half2_rn(c[i][j][0] + bb.x, c[i][j][1] + bb.y);
            __half2 v1 = __floats2half2_rn(c[i][j][2] + bb.x, c[i][j][3] + bb.y);
            if (r0 < N_NODES) *(__half2*)(g_h16A + (size_t)r0 * HID + n) = v0;
            if (r1 < N_NODES) *(__half2*)(g_h16A + (size_t)r1 * HID + n) = v1;
        }
    }
}

// ---------------- column mean + hypernetwork scale ----------------
__global__ void col_partial(int sel) {
    const __half* __restrict__ h = sel ? g_h16B : g_h16A;
    float s = 0.f;
    int cidx = threadIdx.x;
    for (int r = blockIdx.x; r < N_NODES; r += gridDim.x)
        s += __half2float(h[(size_t)r * HID + cidx]);
    g_part[blockIdx.x * HID + cidx] = s;
}

__global__ void mk_scale(const float* __restrict__ W1, const float* __restrict__ b1,
                         const float* __restrict__ W2, const float* __restrict__ b2) {
    __shared__ float g[HID];
    __shared__ float t1[HID];
    int j = threadIdx.x;
    float s = 0.f;
    for (int b = 0; b < NPART; b++) s += g_part[b * HID + j];
    g[j] = s * (1.0f / (float)N_NODES);
    __syncthreads();
    float a = b1[j];
    for (int k = 0; k < HID; k++) a += g[k] * W1[k * HID + j];
    t1[j] = fmaxf(a, 0.f);
    __syncthreads();
    float o = b2[j];
    for (int k = 0; k < HID; k++) o += t1[k] * W2[k * HID + j];
    g_scale[j] = o;
}

// ---------------- aggregation ----------------
__device__ __forceinline__ void acc8(float* a, uint4 v) {
    __half2 h0 = *reinterpret_cast<__half2*>(&v.x);
    __half2 h1 = *reinterpret_cast<__half2*>(&v.y);
    __half2 h2 = *reinterpret_cast<__half2*>(&v.z);
    __half2 h3 = *reinterpret_cast<__half2*>(&v.w);
    float2 f0 = __half22float2(h0), f1 = __half22float2(h1);
    float2 f2 = __half22float2(h2), f3 = __half22float2(h3);
    a[0] += f0.x; a[1] += f0.y; a[2] += f1.x; a[3] += f1.y;
    a[4] += f2.x; a[5] += f2.y; a[6] += f3.x; a[7] += f3.y;
}

__device__ __forceinline__ void seg_sum(const int* __restrict__ ids, int beg, int m,
                                        const __half* __restrict__ h,
                                        int lane, float* acc) {
    const int half = lane >> 4;
    const int cpos = lane & 15;
    for (int c = 0; c < m; c += 32) {
        int rem = m - c;
        if (rem > 32) rem = 32;
        int myid = (lane < rem) ? ids[beg + c + lane] : 0;
        int t = 0;
        for (; t + 8 <= rem; t += 8) {
#pragma unroll
            for (int p = 0; p < 4; p++) {
                int id = __shfl_sync(0xffffffffu, myid, t + 2 * p + half);
                uint4 v = *(const uint4*)(h + (size_t)id * HID + cpos * 8);
                acc8(acc, v);
            }
        }
        for (; t < rem; t += 2) {
            int idx = t + half;
            bool valid = idx < rem;
            int id = __shfl_sync(0xffffffffu, myid, valid ? idx : t);
            uint4 v = *(const uint4*)(h + (size_t)id * HID + cpos * 8);
            if (valid) acc8(acc, v);
        }
    }
#pragma unroll
    for (int i = 0; i < 8; i++)
        acc[i] += __shfl_xor_sync(0xffffffffu, acc[i], 16);
}

__global__ void edge_agg(int sel) {
    const __half* __restrict__ h = sel ? g_h16B : g_h16A;
    int w = (blockIdx.x * blockDim.x + threadIdx.x) >> 5;
    int lane = threadIdx.x & 31;
    if (w >= N_EDGES) return;
    int beg = g_eoff[w], end = g_eoff[w + 1];
    int m = end - beg;
    float acc[8] = {0.f, 0.f, 0.f, 0.f, 0.f, 0.f, 0.f, 0.f};
    seg_sum(g_enodes, beg, m, h, lane, acc);
    if (lane < 16) {
        float inv = 1.0f / fmaxf((float)m, 1.0f);
        __half2 p0 = __floats2half2_rn(acc[0] * inv, acc[1] * inv);
        __half2 p1 = __floats2half2_rn(acc[2] * inv, acc[3] * inv);
        __half2 p2 = __floats2half2_rn(acc[4] * inv, acc[5] * inv);
        __half2 p3 = __floats2half2_rn(acc[6] * inv, acc[7] * inv);
        uint4 u;
        u.x = *reinterpret_cast<unsigned*>(&p0);
        u.y = *reinterpret_cast<unsigned*>(&p1);
        u.z = *reinterpret_cast<unsigned*>(&p2);
        u.w = *reinterpret_cast<unsigned*>(&p3);
        ((uint4*)(g_ef16 + (size_t)w * HID))[lane] = u;
    }
}

__global__ void node_agg(float* __restrict__ out_arg, int to_out) {
    int w = (blockIdx.x * blockDim.x + threadIdx.x) >> 5;
    int lane = threadIdx.x & 31;
    if (w >= N_NODES) return;
    int beg = g_noff[w], end = g_noff[w + 1];
    int m = end - beg;
    float acc[8] = {0.f, 0.f, 0.f, 0.f, 0.f, 0.f, 0.f, 0.f};
    seg_sum(g_nedges, beg, m, g_ef16, lane, acc);
    if (lane < 16) {
        float inv = 1.0f / fmaxf((float)m, 1.0f);
        float4 s0 = ((const float4*)g_scale)[lane * 2];
        float4 s1 = ((const float4*)g_scale)[lane * 2 + 1];
        float r0 = fmaxf(acc[0] * inv * s0.x, 0.f);
        float r1 = fmaxf(acc[1] * inv * s0.y, 0.f);
        float r2 = fmaxf(acc[2] * inv * s0.z, 0.f);
        float r3 = fmaxf(acc[3] * inv * s0.w, 0.f);
        float r4 = fmaxf(acc[4] * inv * s1.x, 0.f);
        float r5 = fmaxf(acc[5] * inv * s1.y, 0.f);
        float r6 = fmaxf(acc[6] * inv * s1.z, 0.f);
        float r7 = fmaxf(acc[7] * inv * s1.w, 0.f);
        if (to_out) {
            float* orow = out_arg + (size_t)w * HID + lane * 8;
            *(float4*)orow = make_float4(r0, r1, r2, r3);
            *(float4*)(orow + 4) = make_float4(r4, r5, r6, r7);
        } else {
            __half2 p0 = __floats2half2_rn(r0, r1);
            __half2 p1 = __floats2half2_rn(r2, r3);
            __half2 p2 = __floats2half2_rn(r4, r5);
            __half2 p3 = __floats2half2_rn(r6, r7);
            uint4 u;
            u.x = *reinterpret_cast<unsigned*>(&p0);
            u.y = *reinterpret_cast<unsigned*>(&p1);
            u.z = *reinterpret_cast<unsigned*>(&p2);
            u.w = *reinterpret_cast<unsigned*>(&p3);
            ((uint4*)(g_h16B + (size_t)w * HID))[lane] = u;
        }
    }
}

// ---------------- launch ----------------
extern "C" void kernel_launch(void* const* d_in, const int* in_sizes, int n_in,
                              void* d_out, int out_size) {
    const float* text = (const float*)d_in[0];
    const float* Wp   = (const float*)d_in[1];
    const float* bp   = (const float*)d_in[2];
    const float* W1a  = (const float*)d_in[3];
    const float* b1a  = (const float*)d_in[4];
    const float* W2a  = (const float*)d_in[5];
    const float* b2a  = (const float*)d_in[6];
    const float* W1b  = (const float*)d_in[7];
    const float* b1b  = (const float*)d_in[8];
    const float* W2b  = (const float*)d_in[9];
    const float* b2b  = (const float*)d_in[10];
    const int* node_idx = (const int*)d_in[11];
    const int* edge_idx = (const int*)d_in[12];

    const int SMEM_GEMM = (2 * ATILE + 2 * WBUF) * 2;  // 110592 B

    static cudaStream_t s2 = nullptr;
    static cudaEvent_t ev0, evCSR, evG, evS1, evN0, evS2;
    if (!s2) {
        cudaStreamCreateWithFlags(&s2, cudaStreamNonBlocking);
        cudaEventCreateWithFlags(&ev0,   cudaEventDisableTiming);
        cudaEventCreateWithFlags(&evCSR, cudaEventDisableTiming);
        cudaEventCreateWithFlags(&evG,   cudaEventDisableTiming);
        cudaEventCreateWithFlags(&evS1,  cudaEventDisableTiming);
        cudaEventCreateWithFlags(&evN0,  cudaEventDisableTiming);
        cudaEventCreateWithFlags(&evS2,  cudaEventDisableTiming);
        cudaFuncSetAttribute(gemm_mma,
            cudaFuncAttributeMaxDynamicSharedMemorySize, SMEM_GEMM);
    }

    cudaEventRecord(ev0, 0);
    cudaStreamWaitEvent(s2, ev0, 0);

    // launches #1,#2 (s2), #3 (main), #4 (main) -> ncu profiles the 4th = gemm_mma
    zero_counts<<<NBN, 256, 0, s2>>>();
    hist_kernel<<<NBI, 256, 0, s2>>>(node_idx, edge_idx);
    w_prep<<<(TD * HID + 255) / 256, 256>>>(Wp);
    gemm_mma<<<(N_NODES + 127) / 128, 256, SMEM_GEMM>>>(text, bp);
    cudaEventRecord(evG, 0);

    // rest of CSR chain on s2 (device-side concurrent with gemm)
    segB<<<NBE + NBN, 256, 0, s2>>>();
    scanB<<<2, 512, 0, s2>>>();
    scanfB<<<NBE + NBN, 256, 0, s2>>>();
    csr_fill<<<NBI, 256, 0, s2>>>(node_idx, edge_idx);
    cudaEventRecord(evCSR, s2);

    // layer-1 stats on s2 overlap edge_agg on main
    cudaStreamWaitEvent(s2, evG, 0);
    col_partial<<<NPART, 128, 0, s2>>>(0);
    mk_scale<<<1, 128, 0, s2>>>(W1a, b1a, W2a, b2a);
    cudaEventRecord(evS1, s2);

    cudaStreamWaitEvent((cudaStream_t)0, evCSR, 0);
    edge_agg<<<N_EDGES / 8, 256>>>(0);
    cudaStreamWaitEvent((cudaStream_t)0, evS1, 0);
    node_agg<<<N_NODES / 8, 256>>>((float*)d_out, 0);
    cudaEventRecord(evN0, 0);

    // layer 2
    cudaStreamWaitEvent(s2, evN0, 0);
    col_partial<<<NPART, 128, 0, s2>>>(1);
    mk_scale<<<1, 128, 0, s2>>>(W1b, b1b, W2b, b2b);
    cudaEventRecord(evS2, s2);

    edge_agg<<<N_EDGES / 8, 256>>>(1);
    cudaStreamWaitEvent((cudaStream_t)0, evS2, 0);
    node_agg<<<N_NODES / 8, 256>>>((float*)d_out, 1);
}

// round 7
// speedup vs baseline: 1.2262x; 1.2262x over previous
#include <cuda_runtime.h>
#include <cuda_fp16.h>
#include <cuda_bf16.h>
#include <cstdint>

#define N_NODES 100000
#define N_EDGES 20000
#define N_INC   800000
#define TD      384
#define HID     128
#define NPART   1024
#define NBE     79
#define NBN     391
#define NBI     3125

// ---------------- device scratch ----------------
__device__ __align__(16) __half g_h16A[N_NODES * HID];
__device__ __align__(16) __half g_h16B[N_NODES * HID];
__device__ __align__(16) __half g_ef16[N_EDGES * HID];
__device__ __align__(16) __half g_Wt16[HID * TD];   // W transposed [n][k] fp16
__device__ int   g_ecnt[N_EDGES];
__device__ int   g_ncnt[N_NODES];
__device__ int   g_ecur[N_EDGES];
__device__ int   g_ncur[N_NODES];
__device__ int   g_eoff[N_EDGES + 1];
__device__ int   g_noff[N_NODES + 1];
__device__ int   g_enodes[N_INC];
__device__ int   g_nedges[N_INC];
__device__ int   g_bsumE[128];
__device__ int   g_bsumN[512];
__device__ float g_part[NPART * HID];
__device__ __align__(16) float g_scale[HID];

// ---------------- CSR construction ----------------
__global__ void zero_counts() {
    int i = blockIdx.x * blockDim.x + threadIdx.x;
    if (i < N_EDGES) { g_ecnt[i] = 0; g_ecur[i] = 0; }
    if (i < N_NODES) { g_ncnt[i] = 0; g_ncur[i] = 0; }
}

__global__ void hist_kernel(const int* __restrict__ ni, const int* __restrict__ ei) {
    int i = blockIdx.x * blockDim.x + threadIdx.x;
    if (i < N_INC) {
        atomicAdd(&g_ecnt[ei[i]], 1);
        atomicAdd(&g_ncnt[ni[i]], 1);
    }
}

__global__ void segB() {
    int b = blockIdx.x;
    const int* __restrict__ cnt;
    int n;
    int* bs;
    if (b < NBE) { cnt = g_ecnt; n = N_EDGES; bs = g_bsumE; }
    else { b -= NBE; cnt = g_ncnt; n = N_NODES; bs = g_bsumN; }
    __shared__ int s[256];
    int t = threadIdx.x;
    int i = b * 256 + t;
    s[t] = (i < n) ? cnt[i] : 0;
    __syncthreads();
    for (int o = 128; o > 0; o >>= 1) {
        if (t < o) s[t] += s[t + o];
        __syncthreads();
    }
    if (t == 0) bs[b] = s[0];
}

__global__ void scanB() {
    int* bs = blockIdx.x ? g_bsumN : g_bsumE;
    int nb = blockIdx.x ? NBN : NBE;
    __shared__ int s[512];
    int t = threadIdx.x;
    int v = (t < nb) ? bs[t] : 0;
    s[t] = v;
    __syncthreads();
    for (int o = 1; o < 512; o <<= 1) {
        int x = (t >= o) ? s[t - o] : 0;
        __syncthreads();
        s[t] += x;
        __syncthreads();
    }
    if (t < nb) bs[t] = s[t] - v;
}

__global__ void scanfB() {
    int b = blockIdx.x;
    const int* __restrict__ cnt;
    const int* bs;
    int* off;
    int n;
    if (b < NBE) { cnt = g_ecnt; bs = g_bsumE; off = g_eoff; n = N_EDGES; }
    else { b -= NBE; cnt = g_ncnt; bs = g_bsumN; off = g_noff; n = N_NODES; }
    __shared__ int s[256];
    int t = threadIdx.x;
    int i = b * 256 + t;
    int v = (i < n) ? cnt[i] : 0;
    s[t] = v;
    __syncthreads();
    for (int o = 1; o < 256; o <<= 1) {
        int x = (t >= o) ? s[t - o] : 0;
        __syncthreads();
        s[t] += x;
        __syncthreads();
    }
    if (i < n) off[i] = bs[b] + s[t] - v;
    if (i == 0) off[n] = N_INC;
}

__global__ void csr_fill(const int* __restrict__ ni, const int* __restrict__ ei) {
    int i = blockIdx.x * blockDim.x + threadIdx.x;
    if (i >= N_INC) return;
    int e = ei[i], n = ni[i];
    int pe = g_eoff[e] + atomicAdd(&g_ecur[e], 1);
    g_enodes[pe] = n;
    int pn = g_noff[n] + atomicAdd(&g_ncur[n], 1);
    g_nedges[pn] = e;
}

// ---------------- W prep: fp32 [k][n] -> fp16 transposed [n][k] ----------------
__global__ void w_prep(const float* __restrict__ W) {
    int i = blockIdx.x * blockDim.x + threadIdx.x;
    if (i >= TD * HID) return;
    int n = i & (HID - 1);
    int k = i >> 7;
    g_Wt16[n * TD + k] = __float2half_rn(W[k * HID + n]);
}

// ---------------- fp16 single-pass tensor-core GEMM ----------------
// h16A[M,128] = A[M,384] @ W[384,128] + bias.
// Block 128x128, KT=64, 256 thr = 8 warps (4m x 2n), warp tile 32x64.
// fp16 inputs (11-bit mantissa: dot rel-err ~1e-4), fp32 accumulators.
#define SSTR 72
#define KT   64

#define LDSM4(r, addr) \
    asm volatile("ldmatrix.sync.aligned.m8n8.x4.shared.b16 {%0,%1,%2,%3}, [%4];" \
        : "=r"((r)[0]), "=r"((r)[1]), "=r"((r)[2]), "=r"((r)[3]) : "r"(addr))

#define MMA16816H(c, a, b0, b1) \
    asm volatile("mma.sync.aligned.m16n8k16.row.col.f32.f16.f16.f32 " \
        "{%0,%1,%2,%3},{%4,%5,%6,%7},{%8,%9},{%0,%1,%2,%3};" \
        : "+f"((c)[0]), "+f"((c)[1]), "+f"((c)[2]), "+f"((c)[3]) \
        : "r"((a)[0]), "r"((a)[1]), "r"((a)[2]), "r"((a)[3]), "r"(b0), "r"(b1))

__global__ void __launch_bounds__(256, 2) gemm_mma(
    const float* __restrict__ A, const float* __restrict__ bias) {
    extern __shared__ char dynsmem[];
    __half* sA = (__half*)dynsmem;             // [128][72]
    __half* sW = sA + 128 * SSTR;              // [n][k] [128][72]

    const int tid = threadIdx.x;
    const int lane = tid & 31;
    const int wid = tid >> 5;
    const int wr = wid >> 1;
    const int wc = wid & 1;
    const int bm = blockIdx.x * 128;

    const unsigned sb = (unsigned)__cvta_generic_to_shared(dynsmem);
    const unsigned Ab = sb;
    const unsigned Wb = sb + 128 * SSTR * 2;

    const int aRow = ((lane >> 3) & 1) * 8 + (lane & 7);
    const int aColH = (lane >> 4) * 8;
    const unsigned aOff0 = (unsigned)(((wr * 32 + 0  + aRow) * SSTR + aColH) * 2);
    const unsigned aOff1 = (unsigned)(((wr * 32 + 16 + aRow) * SSTR + aColH) * 2);
    const int bRow = (lane >> 4) * 8 + (lane & 7);
    const int bColH = ((lane >> 3) & 1) * 8;
    const unsigned bOff = (unsigned)(((wc * 64 + bRow) * SSTR + bColH) * 2);

    const int lm = tid >> 1;
    const int lk = (tid & 1) * 32;
    int arow = bm + lm;
    if (arow >= N_NODES) arow = N_NODES - 1;
    const float* Ap = A + (size_t)arow * TD + lk;
    const __half* Wp = g_Wt16 + lm * TD + lk;

    float c[2][8][4];
#pragma unroll
    for (int i = 0; i < 2; i++)
#pragma unroll
        for (int j = 0; j < 8; j++)
#pragma unroll
            for (int q = 0; q < 4; q++) c[i][j][q] = 0.f;

    for (int t = 0; t < TD / KT; t++) {
        const int k0 = t * KT;
        // A tile: fp32 load -> fp16 smem
#pragma unroll
        for (int cc = 0; cc < 8; cc++) {
            float4 v = *(const float4*)(Ap + k0 + cc * 4);
            __half2 p0 = __floats2half2_rn(v.x, v.y);
            __half2 p1 = __floats2half2_rn(v.z, v.w);
            int so = lm * SSTR + lk + cc * 4;
            *(__half2*)(sA + so)     = p0;
            *(__half2*)(sA + so + 2) = p1;
        }
        // W tile: already fp16/transposed; bulk copy
#pragma unroll
        for (int cc = 0; cc < 4; cc++) {
            uint4 vw = *(const uint4*)(Wp + k0 + cc * 8);
            *(uint4*)(sW + lm * SSTR + lk + cc * 8) = vw;
        }
        __syncthreads();

#pragma unroll
        for (int kk = 0; kk < KT / 16; kk++) {
            const unsigned ko = kk * 32;
            unsigned a[2][4];
            LDSM4(a[0], Ab + aOff0 + ko);
            LDSM4(a[1], Ab + aOff1 + ko);
#pragma unroll
            for (int jj = 0; jj < 4; jj++) {
                unsigned b[4];
                LDSM4(b, Wb + bOff + jj * (16 * SSTR * 2) + ko);
#pragma unroll
                for (int i = 0; i < 2; i++) {
                    MMA16816H(c[i][2 * jj],     a[i], b[0], b[1]);
                    MMA16816H(c[i][2 * jj + 1], a[i], b[2], b[3]);
                }
            }
        }
        __syncthreads();
    }

#pragma unroll
    for (int i = 0; i < 2; i++) {
        int r0 = bm + wr * 32 + i * 16 + (lane >> 2);
        int r1 = r0 + 8;
#pragma unroll
        for (int j = 0; j < 8; j++) {
            int n = wc * 64 + j * 8 + (lane & 3) * 2;
            float2 bb = *(const float2*)(bias + n);
            __half2 v0 = __floats2half2_rn(c[i][j][0] + bb.x, c[i][j][1] + bb.y);
            __half2 v1 = __floats2half2_rn(c[i][j][2] + bb.x, c[i][j][3] + bb.y);
            if (r0 < N_NODES) *(__half2*)(g_h16A + (size_t)r0 * HID + n) = v0;
            if (r1 < N_NODES) *(__half2*)(g_h16A + (size_t)r1 * HID + n) = v1;
        }
    }
}

// ---------------- column mean + hypernetwork scale ----------------
__global__ void col_partial(int sel) {
    const __half* __restrict__ h = sel ? g_h16B : g_h16A;
    float s = 0.f;
    int cidx = threadIdx.x;
    for (int r = blockIdx.x; r < N_NODES; r += gridDim.x)
        s += __half2float(h[(size_t)r * HID + cidx]);
    g_part[blockIdx.x * HID + cidx] = s;
}

__global__ void mk_scale(const float* __restrict__ W1, const float* __restrict__ b1,
                         const float* __restrict__ W2, const float* __restrict__ b2) {
    __shared__ float g[HID];
    __shared__ float t1[HID];
    int j = threadIdx.x;
    float s = 0.f;
    for (int b = 0; b < NPART; b++) s += g_part[b * HID + j];
    g[j] = s * (1.0f / (float)N_NODES);
    __syncthreads();
    float a = b1[j];
    for (int k = 0; k < HID; k++) a += g[k] * W1[k * HID + j];
    t1[j] = fmaxf(a, 0.f);
    __syncthreads();
    float o = b2[j];
    for (int k = 0; k < HID; k++) o += t1[k] * W2[k * HID + j];
    g_scale[j] = o;
}

// ---------------- aggregation ----------------
__device__ __forceinline__ void acc8(float* a, uint4 v) {
    __half2 h0 = *reinterpret_cast<__half2*>(&v.x);
    __half2 h1 = *reinterpret_cast<__half2*>(&v.y);
    __half2 h2 = *reinterpret_cast<__half2*>(&v.z);
    __half2 h3 = *reinterpret_cast<__half2*>(&v.w);
    float2 f0 = __half22float2(h0), f1 = __half22float2(h1);
    float2 f2 = __half22float2(h2), f3 = __half22float2(h3);
    a[0] += f0.x; a[1] += f0.y; a[2] += f1.x; a[3] += f1.y;
    a[4] += f2.x; a[5] += f2.y; a[6] += f3.x; a[7] += f3.y;
}

__device__ __forceinline__ void seg_sum(const int* __restrict__ ids, int beg, int m,
                                        const __half* __restrict__ h,
                                        int lane, float* acc) {
    const int half = lane >> 4;
    const int cpos = lane & 15;
    for (int c = 0; c < m; c += 32) {
        int rem = m - c;
        if (rem > 32) rem = 32;
        int myid = (lane < rem) ? ids[beg + c + lane] : 0;
        int t = 0;
        for (; t + 8 <= rem; t += 8) {
#pragma unroll
            for (int p = 0; p < 4; p++) {
                int id = __shfl_sync(0xffffffffu, myid, t + 2 * p + half);
                uint4 v = *(const uint4*)(h + (size_t)id * HID + cpos * 8);
                acc8(acc, v);
            }
        }
        for (; t < rem; t += 2) {
            int idx = t + half;
            bool valid = idx < rem;
            int id = __shfl_sync(0xffffffffu, myid, valid ? idx : t);
            uint4 v = *(const uint4*)(h + (size_t)id * HID + cpos * 8);
            if (valid) acc8(acc, v);
        }
    }
#pragma unroll
    for (int i = 0; i < 8; i++)
        acc[i] += __shfl_xor_sync(0xffffffffu, acc[i], 16);
}

__global__ void edge_agg(int sel) {
    const __half* __restrict__ h = sel ? g_h16B : g_h16A;
    int w = (blockIdx.x * blockDim.x + threadIdx.x) >> 5;
    int lane = threadIdx.x & 31;
    if (w >= N_EDGES) return;
    int beg = g_eoff[w], end = g_eoff[w + 1];
    int m = end - beg;
    float acc[8] = {0.f, 0.f, 0.f, 0.f, 0.f, 0.f, 0.f, 0.f};
    seg_sum(g_enodes, beg, m, h, lane, acc);
    if (lane < 16) {
        float inv = 1.0f / fmaxf((float)m, 1.0f);
        __half2 p0 = __floats2half2_rn(acc[0] * inv, acc[1] * inv);
        __half2 p1 = __floats2half2_rn(acc[2] * inv, acc[3] * inv);
        __half2 p2 = __floats2half2_rn(acc[4] * inv, acc[5] * inv);
        __half2 p3 = __floats2half2_rn(acc[6] * inv, acc[7] * inv);
        uint4 u;
        u.x = *reinterpret_cast<unsigned*>(&p0);
        u.y = *reinterpret_cast<unsigned*>(&p1);
        u.z = *reinterpret_cast<unsigned*>(&p2);
        u.w = *reinterpret_cast<unsigned*>(&p3);
        ((uint4*)(g_ef16 + (size_t)w * HID))[lane] = u;
    }
}

__global__ void node_agg(float* __restrict__ out_arg, int to_out) {
    int w = (blockIdx.x * blockDim.x + threadIdx.x) >> 5;
    int lane = threadIdx.x & 31;
    if (w >= N_NODES) return;
    int beg = g_noff[w], end = g_noff[w + 1];
    int m = end - beg;
    float acc[8] = {0.f, 0.f, 0.f, 0.f, 0.f, 0.f, 0.f, 0.f};
    seg_sum(g_nedges, beg, m, g_ef16, lane, acc);
    if (lane < 16) {
        float inv = 1.0f / fmaxf((float)m, 1.0f);
        float4 s0 = ((const float4*)g_scale)[lane * 2];
        float4 s1 = ((const float4*)g_scale)[lane * 2 + 1];
        float r0 = fmaxf(acc[0] * inv * s0.x, 0.f);
        float r1 = fmaxf(acc[1] * inv * s0.y, 0.f);
        float r2 = fmaxf(acc[2] * inv * s0.z, 0.f);
        float r3 = fmaxf(acc[3] * inv * s0.w, 0.f);
        float r4 = fmaxf(acc[4] * inv * s1.x, 0.f);
        float r5 = fmaxf(acc[5] * inv * s1.y, 0.f);
        float r6 = fmaxf(acc[6] * inv * s1.z, 0.f);
        float r7 = fmaxf(acc[7] * inv * s1.w, 0.f);
        if (to_out) {
            float* orow = out_arg + (size_t)w * HID + lane * 8;
            *(float4*)orow = make_float4(r0, r1, r2, r3);
            *(float4*)(orow + 4) = make_float4(r4, r5, r6, r7);
        } else {
            __half2 p0 = __floats2half2_rn(r0, r1);
            __half2 p1 = __floats2half2_rn(r2, r3);
            __half2 p2 = __floats2half2_rn(r4, r5);
            __half2 p3 = __floats2half2_rn(r6, r7);
            uint4 u;
            u.x = *reinterpret_cast<unsigned*>(&p0);
            u.y = *reinterpret_cast<unsigned*>(&p1);
            u.z = *reinterpret_cast<unsigned*>(&p2);
            u.w = *reinterpret_cast<unsigned*>(&p3);
            ((uint4*)(g_h16B + (size_t)w * HID))[lane] = u;
        }
    }
}

// ---------------- launch ----------------
extern "C" void kernel_launch(void* const* d_in, const int* in_sizes, int n_in,
                              void* d_out, int out_size) {
    const float* text = (const float*)d_in[0];
    const float* Wp   = (const float*)d_in[1];
    const float* bp   = (const float*)d_in[2];
    const float* W1a  = (const float*)d_in[3];
    const float* b1a  = (const float*)d_in[4];
    const float* W2a  = (const float*)d_in[5];
    const float* b2a  = (const float*)d_in[6];
    const float* W1b  = (const float*)d_in[7];
    const float* b1b  = (const float*)d_in[8];
    const float* W2b  = (const float*)d_in[9];
    const float* b2b  = (const float*)d_in[10];
    const int* node_idx = (const int*)d_in[11];
    const int* edge_idx = (const int*)d_in[12];

    const int SMEM_GEMM = 2 * 128 * SSTR * 2;  // 36864 B

    static cudaStream_t s2 = nullptr;
    static cudaEvent_t ev0, evCSR, evG, evS1, evN0, evS2;
    if (!s2) {
        cudaStreamCreateWithFlags(&s2, cudaStreamNonBlocking);
        cudaEventCreateWithFlags(&ev0,   cudaEventDisableTiming);
        cudaEventCreateWithFlags(&evCSR, cudaEventDisableTiming);
        cudaEventCreateWithFlags(&evG,   cudaEventDisableTiming);
        cudaEventCreateWithFlags(&evS1,  cudaEventDisableTiming);
        cudaEventCreateWithFlags(&evN0,  cudaEventDisableTiming);
        cudaEventCreateWithFlags(&evS2,  cudaEventDisableTiming);
        cudaFuncSetAttribute(gemm_mma,
            cudaFuncAttributeMaxDynamicSharedMemorySize, SMEM_GEMM);
    }

    cudaEventRecord(ev0, 0);
    cudaStreamWaitEvent(s2, ev0, 0);

    // launches: #1,#2 on s2; #3 w_prep; #4 gemm_mma (ncu profiles the 4th)
    zero_counts<<<NBN, 256, 0, s2>>>();
    hist_kernel<<<NBI, 256, 0, s2>>>(node_idx, edge_idx);
    w_prep<<<(TD * HID + 255) / 256, 256>>>(Wp);
    gemm_mma<<<(N_NODES + 127) / 128, 256, SMEM_GEMM>>>(text, bp);
    cudaEventRecord(evG, 0);

    segB<<<NBE + NBN, 256, 0, s2>>>();
    scanB<<<2, 512, 0, s2>>>();
    scanfB<<<NBE + NBN, 256, 0, s2>>>();
    csr_fill<<<NBI, 256, 0, s2>>>(node_idx, edge_idx);
    cudaEventRecord(evCSR, s2);

    cudaStreamWaitEvent(s2, evG, 0);
    col_partial<<<NPART, 128, 0, s2>>>(0);
    mk_scale<<<1, 128, 0, s2>>>(W1a, b1a, W2a, b2a);
    cudaEventRecord(evS1, s2);

    cudaStreamWaitEvent((cudaStream_t)0, evCSR, 0);
    edge_agg<<<N_EDGES / 8, 256>>>(0);
    cudaStreamWaitEvent((cudaStream_t)0, evS1, 0);
    node_agg<<<N_NODES / 8, 256>>>((float*)d_out, 0);
    cudaEventRecord(evN0, 0);

    cudaStreamWaitEvent(s2, evN0, 0);
    col_partial<<<NPART, 128, 0, s2>>>(1);
    mk_scale<<<1, 128, 0, s2>>>(W1b, b1b, W2b, b2b);
    cudaEventRecord(evS2, s2);

    edge_agg<<<N_EDGES / 8, 256>>>(1);
    cudaStreamWaitEvent((cudaStream_t)0, evS2, 0);
    node_agg<<<N_NODES / 8, 256>>>((float*)d_out, 1);
}